// round 15
// baseline (speedup 1.0000x reference)
#include <cuda_runtime.h>
#include <cuda_fp16.h>
#include <cstdint>

#define NNODES 100000
#define NEDGES 1600000
#define FIN    128
#define HID    64
#define NCLS   40

#define SCAN_BLOCKS 98   // 98 * 1024 >= NNODES

// ---------------- device scratch (allocation-free) ----------------
__device__ int    g_hist[NNODES];
__device__ int    g_rank[NEDGES];          // within-node arrival rank of each edge
__device__ int    g_offs[NNODES];          // block-local exclusive offsets
__device__ int    g_boff[SCAN_BLOCKS];     // per-block base in edge array (atomic chunk)
__device__ int    g_total;                 // chunk-reservation counter
__device__ int    g_csr_src[NEDGES];
__device__ float  g_dinv[NNODES];
__device__ __half g_h1h[(size_t)NNODES * HID];    // (x @ W1) * dinv[row], fp16
__device__ __half g_agg1h[(size_t)NNODES * HID];  // relu(layer-1 agg), fp16
__device__ __half g_h2h[(size_t)NNODES * NCLS];   // (relu_agg1 @ W2) * dinv[row], fp16

// ---------------- helpers ----------------
typedef unsigned long long u64;
__device__ __forceinline__ u64 ffma2(u64 a, u64 b, u64 c) {
    u64 d;
    asm("fma.rn.f32x2 %0, %1, %2, %3;" : "=l"(d) : "l"(a), "l"(b), "l"(c));
    return d;
}
__device__ __forceinline__ u64 pack2(float x) {
    u64 d;
    asm("mov.b64 %0, {%1, %1};" : "=l"(d) : "f"(x));
    return d;
}
union F2 { u64 u; float2 f; };
union W4 { float4 v; struct { u64 lo, hi; } u; };

__device__ __forceinline__ float2 h2tof2(uint32_t h) {
    __half2 hh = *reinterpret_cast<__half2*>(&h);
    return __half22float2(hh);
}

// global CSR range for node n
__device__ __forceinline__ void node_range(int n, int& p0, int& p1) {
    p0 = g_offs[n] + g_boff[n >> 10];
    int m = n + 1;
    if ((m >> 10) == (n >> 10) && m < NNODES)
        p1 = g_offs[m] + g_boff[m >> 10];
    else
        p1 = p0 + g_hist[n];   // last node in block (or globally)
}

// ---------------- CSR build ----------------
__global__ void k_zero() {
    int i = blockIdx.x * blockDim.x + threadIdx.x;
    if (i < NNODES) g_hist[i] = 0;
    if (i == 0) g_total = 0;
}
// histogram that also records each edge's within-node rank (coalesced store)
__global__ void k_hist(const int* __restrict__ dst) {
    int e = blockIdx.x * blockDim.x + threadIdx.x;
    if (e < NEDGES) g_rank[e] = atomicAdd(&g_hist[dst[e]], 1);
}
// block scan + atomic chunk reservation
__global__ void __launch_bounds__(1024) k_scan1() {
    __shared__ int sh[1024];
    int i = blockIdx.x * 1024 + threadIdx.x;
    int h = (i < NNODES) ? g_hist[i] : 0;
    sh[threadIdx.x] = h;
    __syncthreads();
    #pragma unroll
    for (int ofs = 1; ofs < 1024; ofs <<= 1) {
        int v = (threadIdx.x >= ofs) ? sh[threadIdx.x - ofs] : 0;
        __syncthreads();
        sh[threadIdx.x] += v;
        __syncthreads();
    }
    if (i < NNODES) {
        g_offs[i] = sh[threadIdx.x] - h;
        g_dinv[i] = rsqrtf((float)(h + 1));
    }
    if (threadIdx.x == 1023)
        g_boff[blockIdx.x] = atomicAdd(&g_total, sh[1023]);
}
// atomic-free scatter: position fully determined by precomputed rank
__global__ void k_fill(const int* __restrict__ src, const int* __restrict__ dst) {
    int e = blockIdx.x * blockDim.x + threadIdx.x;
    if (e >= NEDGES) return;
    int d = dst[e];
    int pos = g_offs[d] + g_boff[d >> 10] + g_rank[e];
    g_csr_src[pos] = src[e];
}

// ---------------- GEMM1: h1h = (x @ W1) * dinv  (fp16 out) ----------------
// 256 threads, 128-row tile; thread = 8 rows x 4 strided cols; f32x2 packed over K.
// wt pitch 130 + float2 loads -> conflict-free W reads (bank stride c*2 mod 32).
#define XP  132
#define WTP 130
__global__ void __launch_bounds__(256, 2) k_gemm1(const float* __restrict__ x,
                                                  const float* __restrict__ W1) {
    __shared__ float xs[128 * XP];    // 67.6 KB, row-major: xs[r*XP + k]
    __shared__ float wt[HID * WTP];   // 33.3 KB, transposed: wt[c*WTP + k]
    const int tid  = threadIdx.x;
    const int row0 = blockIdx.x * 128;

    // load W1 transposed: W1[k][c] -> wt[c][k]
    #pragma unroll
    for (int i = 0; i < 32; i++) {
        int idx = tid + i * 256;          // [0, 8192)
        int k = idx >> 6, c = idx & 63;
        wt[c * WTP + k] = W1[idx];
    }
    // load x tile (4096 float4), row-major pitched
    #pragma unroll
    for (int i = 0; i < 16; i++) {
        int f = tid + i * 256;
        int r = f >> 5;
        int o = (f & 31) << 2;
        float4 v = make_float4(0.f, 0.f, 0.f, 0.f);
        if (row0 + r < NNODES) v = *(const float4*)(x + (size_t)(row0 + r) * FIN + o);
        *(float4*)(xs + r * XP + o) = v;
    }
    __syncthreads();

    const int rp = tid >> 4;              // 0..15 -> rows rp*8..rp*8+7
    const int cg = tid & 15;              // cols cg + 16j, j=0..3
    const float* xr = xs + (rp * 8) * XP;

    u64 acc[8][4];
    #pragma unroll
    for (int r = 0; r < 8; r++)
        #pragma unroll
        for (int j = 0; j < 4; j++) acc[r][j] = 0ull;

    #pragma unroll 2
    for (int k = 0; k < FIN; k += 4) {
        F2 wlo[4], whi[4];
        #pragma unroll
        for (int j = 0; j < 4; j++) {
            const float* wp = wt + (cg + 16 * j) * WTP + k;
            wlo[j].f = *(const float2*)(wp);
            whi[j].f = *(const float2*)(wp + 2);
        }
        #pragma unroll
        for (int r = 0; r < 8; r++) {
            W4 xv;
            xv.v = *(const float4*)(xr + r * XP + k);
            #pragma unroll
            for (int j = 0; j < 4; j++) {
                acc[r][j] = ffma2(xv.u.lo, wlo[j].u, acc[r][j]);
                acc[r][j] = ffma2(xv.u.hi, whi[j].u, acc[r][j]);
            }
        }
    }

    #pragma unroll
    for (int r = 0; r < 8; r++) {
        int row = row0 + rp * 8 + r;
        if (row >= NNODES) continue;
        float di = g_dinv[row];
        __half* hp = g_h1h + (size_t)row * HID;
        #pragma unroll
        for (int j = 0; j < 4; j++) {
            F2 a; a.u = acc[r][j];
            hp[cg + 16 * j] = __float2half_rn((a.f.x + a.f.y) * di);
        }
    }
}

// ---------------- agg1: agg1h[n] = relu((h1h[n] + sum h1h[src]) * dinv[n] + b1), fp16 ----------------
// 8 lanes per node; lane j owns 8 halves (16B).
__global__ void __launch_bounds__(256) k_agg1(const float* __restrict__ b1) {
    int t = blockIdx.x * 256 + threadIdx.x;
    int n = t >> 3;
    if (n >= NNODES) return;
    int j = t & 7;

    int p0, p1;
    node_range(n, p0, p1);

    float acc[8];
    {   // self-loop seed
        uint4 v = *(const uint4*)(g_h1h + (size_t)n * HID + j * 8);
        float2 f0 = h2tof2(v.x), f1 = h2tof2(v.y), f2 = h2tof2(v.z), f3 = h2tof2(v.w);
        acc[0] = f0.x; acc[1] = f0.y; acc[2] = f1.x; acc[3] = f1.y;
        acc[4] = f2.x; acc[5] = f2.y; acc[6] = f3.x; acc[7] = f3.y;
    }
    int p = p0;
    for (; p + 8 <= p1; p += 8) {
        int s[8];
        #pragma unroll
        for (int q = 0; q < 8; q++) s[q] = g_csr_src[p + q];
        uint4 v[8];
        #pragma unroll
        for (int q = 0; q < 8; q++)
            v[q] = *(const uint4*)(g_h1h + (size_t)s[q] * HID + j * 8);
        #pragma unroll
        for (int q = 0; q < 8; q++) {
            float2 f0 = h2tof2(v[q].x), f1 = h2tof2(v[q].y);
            float2 f2 = h2tof2(v[q].z), f3 = h2tof2(v[q].w);
            acc[0] += f0.x; acc[1] += f0.y; acc[2] += f1.x; acc[3] += f1.y;
            acc[4] += f2.x; acc[5] += f2.y; acc[6] += f3.x; acc[7] += f3.y;
        }
    }
    for (; p < p1; p++) {
        int s = g_csr_src[p];
        uint4 v = *(const uint4*)(g_h1h + (size_t)s * HID + j * 8);
        float2 f0 = h2tof2(v.x), f1 = h2tof2(v.y), f2 = h2tof2(v.z), f3 = h2tof2(v.w);
        acc[0] += f0.x; acc[1] += f0.y; acc[2] += f1.x; acc[3] += f1.y;
        acc[4] += f2.x; acc[5] += f2.y; acc[6] += f3.x; acc[7] += f3.y;
    }
    float di = g_dinv[n];
    float4 bb0 = *(const float4*)(b1 + j * 8);
    float4 bb1 = *(const float4*)(b1 + j * 8 + 4);
    float o0 = fmaxf(fmaf(acc[0], di, bb0.x), 0.f);
    float o1 = fmaxf(fmaf(acc[1], di, bb0.y), 0.f);
    float o2 = fmaxf(fmaf(acc[2], di, bb0.z), 0.f);
    float o3 = fmaxf(fmaf(acc[3], di, bb0.w), 0.f);
    float o4 = fmaxf(fmaf(acc[4], di, bb1.x), 0.f);
    float o5 = fmaxf(fmaf(acc[5], di, bb1.y), 0.f);
    float o6 = fmaxf(fmaf(acc[6], di, bb1.z), 0.f);
    float o7 = fmaxf(fmaf(acc[7], di, bb1.w), 0.f);
    uint4 st;
    __half2* sp = (__half2*)&st;
    sp[0] = __floats2half2_rn(o0, o1);
    sp[1] = __floats2half2_rn(o2, o3);
    sp[2] = __floats2half2_rn(o4, o5);
    sp[3] = __floats2half2_rn(o6, o7);
    *(uint4*)(g_agg1h + (size_t)n * HID + j * 8) = st;
}

// ---------------- GEMM2: h2h = (agg1h @ W2) * dinv  (fp16 in/out) ----------------
#define XS2_PITCH 68
__global__ void __launch_bounds__(256, 2) k_gemm2(const float* __restrict__ W2) {
    __shared__ float xs[128 * XS2_PITCH];  // 34.8 KB
    __shared__ float ws[HID * 64];         // 16 KB (cols padded 40->64)
    const int tid  = threadIdx.x;
    const int row0 = blockIdx.x * 128;

    #pragma unroll
    for (int i = 0; i < 16; i++) {
        int idx = tid + i * 256;
        int k = idx >> 6, c = idx & 63;
        ws[idx] = (c < NCLS) ? W2[k * NCLS + c] : 0.0f;
    }
    #pragma unroll
    for (int i = 0; i < 4; i++) {
        int f = tid + i * 256;            // [0, 1024)
        int r = f >> 3;
        int c = f & 7;
        float v[8] = {0.f, 0.f, 0.f, 0.f, 0.f, 0.f, 0.f, 0.f};
        if (row0 + r < NNODES) {
            uint4 h = *(const uint4*)(g_agg1h + (size_t)(row0 + r) * HID + c * 8);
            float2 f0 = h2tof2(h.x), f1 = h2tof2(h.y), f2 = h2tof2(h.z), f3 = h2tof2(h.w);
            v[0] = f0.x; v[1] = f0.y; v[2] = f1.x; v[3] = f1.y;
            v[4] = f2.x; v[5] = f2.y; v[6] = f3.x; v[7] = f3.y;
        }
        float* xp = xs + r * XS2_PITCH + c * 8;
        *(float4*)(xp)     = make_float4(v[0], v[1], v[2], v[3]);
        *(float4*)(xp + 4) = make_float4(v[4], v[5], v[6], v[7]);
    }
    __syncthreads();

    const int rp = tid >> 4;
    const int cg = tid & 15;
    if (cg >= 10) return;
    const float* wcol = ws + cg * 4;
    const float* xr = xs + (rp * 8) * XS2_PITCH;

    u64 acc[8][2];
    #pragma unroll
    for (int r = 0; r < 8; r++) { acc[r][0] = 0ull; acc[r][1] = 0ull; }

    #pragma unroll 2
    for (int k = 0; k < HID; k += 4) {
        float4 xa[8];
        #pragma unroll
        for (int r = 0; r < 8; r++)
            xa[r] = *(const float4*)(xr + r * XS2_PITCH + k);
        #pragma unroll
        for (int kk = 0; kk < 4; kk++) {
            W4 w;
            w.v = *(const float4*)(wcol + (k + kk) * 64);
            #pragma unroll
            for (int r = 0; r < 8; r++) {
                u64 xv = pack2((&xa[r].x)[kk]);
                acc[r][0] = ffma2(w.u.lo, xv, acc[r][0]);
                acc[r][1] = ffma2(w.u.hi, xv, acc[r][1]);
            }
        }
    }

    #pragma unroll
    for (int r = 0; r < 8; r++) {
        int row = row0 + rp * 8 + r;
        if (row >= NNODES) continue;
        float di = g_dinv[row];
        F2 a0, a1;
        a0.u = acc[r][0]; a1.u = acc[r][1];
        uint2 st;
        __half2* sp = (__half2*)&st;
        sp[0] = __floats2half2_rn(a0.f.x * di, a0.f.y * di);
        sp[1] = __floats2half2_rn(a1.f.x * di, a1.f.y * di);
        *(uint2*)(g_h2h + (size_t)row * NCLS + cg * 4) = st;
    }
}

// ---------------- agg2: out[n] = (h2h[n] + sum h2h[src]) * dinv[n] + b2 ----------------
// 5 lanes per node; lane j owns 8 halves (16B).
__global__ void __launch_bounds__(256) k_agg2(const float* __restrict__ b2,
                                              float* __restrict__ out) {
    int t = blockIdx.x * 256 + threadIdx.x;
    int n = t / 5;
    if (n >= NNODES) return;
    int j = t - n * 5;

    int p0, p1;
    node_range(n, p0, p1);

    float acc[8];
    {
        uint4 v = *(const uint4*)(g_h2h + (size_t)n * NCLS + j * 8);
        float2 f0 = h2tof2(v.x), f1 = h2tof2(v.y), f2 = h2tof2(v.z), f3 = h2tof2(v.w);
        acc[0] = f0.x; acc[1] = f0.y; acc[2] = f1.x; acc[3] = f1.y;
        acc[4] = f2.x; acc[5] = f2.y; acc[6] = f3.x; acc[7] = f3.y;
    }
    int p = p0;
    for (; p + 8 <= p1; p += 8) {
        int s[8];
        #pragma unroll
        for (int q = 0; q < 8; q++) s[q] = g_csr_src[p + q];
        uint4 v[8];
        #pragma unroll
        for (int q = 0; q < 8; q++)
            v[q] = *(const uint4*)(g_h2h + (size_t)s[q] * NCLS + j * 8);
        #pragma unroll
        for (int q = 0; q < 8; q++) {
            float2 f0 = h2tof2(v[q].x), f1 = h2tof2(v[q].y);
            float2 f2 = h2tof2(v[q].z), f3 = h2tof2(v[q].w);
            acc[0] += f0.x; acc[1] += f0.y; acc[2] += f1.x; acc[3] += f1.y;
            acc[4] += f2.x; acc[5] += f2.y; acc[6] += f3.x; acc[7] += f3.y;
        }
    }
    for (; p < p1; p++) {
        int s = g_csr_src[p];
        uint4 v = *(const uint4*)(g_h2h + (size_t)s * NCLS + j * 8);
        float2 f0 = h2tof2(v.x), f1 = h2tof2(v.y), f2 = h2tof2(v.z), f3 = h2tof2(v.w);
        acc[0] += f0.x; acc[1] += f0.y; acc[2] += f1.x; acc[3] += f1.y;
        acc[4] += f2.x; acc[5] += f2.y; acc[6] += f3.x; acc[7] += f3.y;
    }
    float di = g_dinv[n];
    float4 bb0 = *(const float4*)(b2 + j * 8);
    float4 bb1 = *(const float4*)(b2 + j * 8 + 4);
    float* op = out + (size_t)n * NCLS + j * 8;
    *(float4*)(op)     = make_float4(fmaf(acc[0], di, bb0.x), fmaf(acc[1], di, bb0.y),
                                     fmaf(acc[2], di, bb0.z), fmaf(acc[3], di, bb0.w));
    *(float4*)(op + 4) = make_float4(fmaf(acc[4], di, bb1.x), fmaf(acc[5], di, bb1.y),
                                     fmaf(acc[6], di, bb1.z), fmaf(acc[7], di, bb1.w));
}

// ---------------- launch ----------------
extern "C" void kernel_launch(void* const* d_in, const int* in_sizes, int n_in,
                              void* d_out, int out_size) {
    const float* x   = (const float*)d_in[0];
    const int*   ei  = (const int*)d_in[1];
    const float* W1  = (const float*)d_in[2];
    const float* b1  = (const float*)d_in[3];
    const float* W2  = (const float*)d_in[4];
    const float* b2  = (const float*)d_in[5];
    float* out = (float*)d_out;

    const int* src = ei;
    const int* dst = ei + NEDGES;

    // CSR build + dinv (rank-based fill: no atomics in fill)
    k_zero<<<(NNODES + 255) / 256, 256>>>();
    k_hist<<<(NEDGES + 255) / 256, 256>>>(dst);
    k_scan1<<<SCAN_BLOCKS, 1024>>>();
    k_fill<<<(NEDGES + 255) / 256, 256>>>(src, dst);

    // layer 1
    k_gemm1<<<(NNODES + 127) / 128, 256>>>(x, W1);
    k_agg1<<<(NNODES * 8 + 255) / 256, 256>>>(b1);

    // layer 2
    k_gemm2<<<(NNODES + 127) / 128, 256>>>(W2);
    k_agg2<<<(NNODES * 5 + 255) / 256, 256>>>(b2, out);
}

// round 16
// speedup vs baseline: 1.1403x; 1.1403x over previous
#include <cuda_runtime.h>
#include <cuda_fp16.h>
#include <mma.h>
#include <cstdint>

using namespace nvcuda;

#define NNODES 100000
#define NEDGES 1600000
#define FIN    128
#define HID    64
#define NCLS   40

#define SCAN_BLOCKS 98   // 98 * 1024 >= NNODES

// ---------------- device scratch (allocation-free) ----------------
__device__ int    g_hist[NNODES];
__device__ int    g_rank[NEDGES];          // within-node arrival rank of each edge
__device__ int    g_offs[NNODES];          // block-local exclusive offsets
__device__ int    g_boff[SCAN_BLOCKS];     // per-block base in edge array (atomic chunk)
__device__ int    g_total;                 // chunk-reservation counter
__device__ int    g_csr_src[NEDGES];
__device__ float  g_dinv[NNODES];
__device__ __half g_h1h[(size_t)NNODES * HID];    // (x @ W1) * dinv[row], fp16
__device__ __half g_agg1h[(size_t)NNODES * HID];  // relu(layer-1 agg), fp16
__device__ __half g_h2h[(size_t)NNODES * NCLS];   // (relu_agg1 @ W2) * dinv[row], fp16

// ---------------- helpers ----------------
typedef unsigned long long u64;
__device__ __forceinline__ u64 ffma2(u64 a, u64 b, u64 c) {
    u64 d;
    asm("fma.rn.f32x2 %0, %1, %2, %3;" : "=l"(d) : "l"(a), "l"(b), "l"(c));
    return d;
}
__device__ __forceinline__ u64 pack2(float x) {
    u64 d;
    asm("mov.b64 %0, {%1, %1};" : "=l"(d) : "f"(x));
    return d;
}
union F2 { u64 u; float2 f; };
union W4 { float4 v; struct { u64 lo, hi; } u; };

__device__ __forceinline__ float2 h2tof2(uint32_t h) {
    __half2 hh = *reinterpret_cast<__half2*>(&h);
    return __half22float2(hh);
}

// global CSR range for node n
__device__ __forceinline__ void node_range(int n, int& p0, int& p1) {
    p0 = g_offs[n] + g_boff[n >> 10];
    int m = n + 1;
    if ((m >> 10) == (n >> 10) && m < NNODES)
        p1 = g_offs[m] + g_boff[m >> 10];
    else
        p1 = p0 + g_hist[n];   // last node in block (or globally)
}

// ---------------- CSR build ----------------
__global__ void k_zero() {
    int i = blockIdx.x * blockDim.x + threadIdx.x;
    if (i < NNODES) g_hist[i] = 0;
    if (i == 0) g_total = 0;
}
// histogram that also records each edge's within-node rank (coalesced store)
__global__ void k_hist(const int* __restrict__ dst) {
    int e = blockIdx.x * blockDim.x + threadIdx.x;
    if (e < NEDGES) g_rank[e] = atomicAdd(&g_hist[dst[e]], 1);
}
// block scan + atomic chunk reservation
__global__ void __launch_bounds__(1024) k_scan1() {
    __shared__ int sh[1024];
    int i = blockIdx.x * 1024 + threadIdx.x;
    int h = (i < NNODES) ? g_hist[i] : 0;
    sh[threadIdx.x] = h;
    __syncthreads();
    #pragma unroll
    for (int ofs = 1; ofs < 1024; ofs <<= 1) {
        int v = (threadIdx.x >= ofs) ? sh[threadIdx.x - ofs] : 0;
        __syncthreads();
        sh[threadIdx.x] += v;
        __syncthreads();
    }
    if (i < NNODES) {
        g_offs[i] = sh[threadIdx.x] - h;
        g_dinv[i] = rsqrtf((float)(h + 1));
    }
    if (threadIdx.x == 1023)
        g_boff[blockIdx.x] = atomicAdd(&g_total, sh[1023]);
}
// atomic-free scatter: position fully determined by precomputed rank
__global__ void k_fill(const int* __restrict__ src, const int* __restrict__ dst) {
    int e = blockIdx.x * blockDim.x + threadIdx.x;
    if (e >= NEDGES) return;
    int d = dst[e];
    int pos = g_offs[d] + g_boff[d >> 10] + g_rank[e];
    g_csr_src[pos] = src[e];
}

// ---------------- GEMM1 (tensor cores): h1h = (x @ W1) * dinv  (fp16 out) ----------------
// 256 threads (8 warps), 128-row tile. Warp w computes rows w*16..w*16+15 x 64 cols
// via wmma m16n16k16 (fp16 in, fp32 accum).
#define XH_LDM 136   // halves; multiple of 8
#define WH_LDM 72    // halves; multiple of 8
__global__ void __launch_bounds__(256, 2) k_gemm1(const float* __restrict__ x,
                                                  const float* __restrict__ W1) {
    __shared__ __half xh[128 * XH_LDM];   // 34.8 KB
    __shared__ __half wh[FIN * WH_LDM];   // 18.4 KB
    __shared__ float  sbuf[128 * HID];    // 32 KB (fp32 staging)
    const int tid  = threadIdx.x;
    const int row0 = blockIdx.x * 128;

    // W1 [128][64] fp32 -> wh fp16
    #pragma unroll
    for (int i = 0; i < 32; i++) {
        int idx = tid + i * 256;          // [0, 8192)
        int k = idx >> 6, c = idx & 63;
        wh[k * WH_LDM + c] = __float2half_rn(W1[idx]);
    }
    // x tile [128][128] fp32 -> xh fp16
    #pragma unroll
    for (int i = 0; i < 16; i++) {
        int f = tid + i * 256;            // [0, 4096) float4 units
        int r = f >> 5;
        int o = (f & 31) << 2;
        float4 v = make_float4(0.f, 0.f, 0.f, 0.f);
        if (row0 + r < NNODES) v = *(const float4*)(x + (size_t)(row0 + r) * FIN + o);
        __half2* hp = (__half2*)(xh + r * XH_LDM + o);
        hp[0] = __floats2half2_rn(v.x, v.y);
        hp[1] = __floats2half2_rn(v.z, v.w);
    }
    __syncthreads();

    const int w = tid >> 5;

    wmma::fragment<wmma::accumulator, 16, 16, 16, float> c[4];
    #pragma unroll
    for (int j = 0; j < 4; j++) wmma::fill_fragment(c[j], 0.0f);

    #pragma unroll
    for (int k8 = 0; k8 < FIN / 16; k8++) {
        wmma::fragment<wmma::matrix_a, 16, 16, 16, __half, wmma::row_major> a;
        wmma::load_matrix_sync(a, xh + (w * 16) * XH_LDM + k8 * 16, XH_LDM);
        #pragma unroll
        for (int j = 0; j < 4; j++) {
            wmma::fragment<wmma::matrix_b, 16, 16, 16, __half, wmma::row_major> b;
            wmma::load_matrix_sync(b, wh + (k8 * 16) * WH_LDM + j * 16, WH_LDM);
            wmma::mma_sync(c[j], a, b, c[j]);
        }
    }

    // stage fp32, then scale + convert + coalesced write
    #pragma unroll
    for (int j = 0; j < 4; j++)
        wmma::store_matrix_sync(sbuf + (w * 16) * HID + j * 16, c[j], HID, wmma::mem_row_major);
    __syncwarp();

    const int lane = tid & 31;
    const int lr   = lane >> 1;         // 0..15
    const int hs   = lane & 1;          // half-row selector
    const int row  = w * 16 + lr;
    const int grow = row0 + row;
    if (grow < NNODES) {
        float di = g_dinv[grow];
        const float* sp = sbuf + row * HID + hs * 32;
        __half* hp = g_h1h + (size_t)grow * HID + hs * 32;
        #pragma unroll
        for (int q = 0; q < 4; q++) {
            float4 v0 = *(const float4*)(sp + q * 8);
            float4 v1 = *(const float4*)(sp + q * 8 + 4);
            uint4 st;
            __half2* s2 = (__half2*)&st;
            s2[0] = __floats2half2_rn(v0.x * di, v0.y * di);
            s2[1] = __floats2half2_rn(v0.z * di, v0.w * di);
            s2[2] = __floats2half2_rn(v1.x * di, v1.y * di);
            s2[3] = __floats2half2_rn(v1.z * di, v1.w * di);
            *(uint4*)(hp + q * 8) = st;
        }
    }
}

// ---------------- agg1: agg1h[n] = relu((h1h[n] + sum h1h[src]) * dinv[n] + b1), fp16 ----------------
// 8 lanes per node; lane j owns 8 halves (16B).
__global__ void __launch_bounds__(256) k_agg1(const float* __restrict__ b1) {
    int t = blockIdx.x * 256 + threadIdx.x;
    int n = t >> 3;
    if (n >= NNODES) return;
    int j = t & 7;

    int p0, p1;
    node_range(n, p0, p1);

    float acc[8];
    {   // self-loop seed
        uint4 v = *(const uint4*)(g_h1h + (size_t)n * HID + j * 8);
        float2 f0 = h2tof2(v.x), f1 = h2tof2(v.y), f2 = h2tof2(v.z), f3 = h2tof2(v.w);
        acc[0] = f0.x; acc[1] = f0.y; acc[2] = f1.x; acc[3] = f1.y;
        acc[4] = f2.x; acc[5] = f2.y; acc[6] = f3.x; acc[7] = f3.y;
    }
    int p = p0;
    for (; p + 8 <= p1; p += 8) {
        int s[8];
        #pragma unroll
        for (int q = 0; q < 8; q++) s[q] = g_csr_src[p + q];
        uint4 v[8];
        #pragma unroll
        for (int q = 0; q < 8; q++)
            v[q] = *(const uint4*)(g_h1h + (size_t)s[q] * HID + j * 8);
        #pragma unroll
        for (int q = 0; q < 8; q++) {
            float2 f0 = h2tof2(v[q].x), f1 = h2tof2(v[q].y);
            float2 f2 = h2tof2(v[q].z), f3 = h2tof2(v[q].w);
            acc[0] += f0.x; acc[1] += f0.y; acc[2] += f1.x; acc[3] += f1.y;
            acc[4] += f2.x; acc[5] += f2.y; acc[6] += f3.x; acc[7] += f3.y;
        }
    }
    for (; p < p1; p++) {
        int s = g_csr_src[p];
        uint4 v = *(const uint4*)(g_h1h + (size_t)s * HID + j * 8);
        float2 f0 = h2tof2(v.x), f1 = h2tof2(v.y), f2 = h2tof2(v.z), f3 = h2tof2(v.w);
        acc[0] += f0.x; acc[1] += f0.y; acc[2] += f1.x; acc[3] += f1.y;
        acc[4] += f2.x; acc[5] += f2.y; acc[6] += f3.x; acc[7] += f3.y;
    }
    float di = g_dinv[n];
    float4 bb0 = *(const float4*)(b1 + j * 8);
    float4 bb1 = *(const float4*)(b1 + j * 8 + 4);
    float o0 = fmaxf(fmaf(acc[0], di, bb0.x), 0.f);
    float o1 = fmaxf(fmaf(acc[1], di, bb0.y), 0.f);
    float o2 = fmaxf(fmaf(acc[2], di, bb0.z), 0.f);
    float o3 = fmaxf(fmaf(acc[3], di, bb0.w), 0.f);
    float o4 = fmaxf(fmaf(acc[4], di, bb1.x), 0.f);
    float o5 = fmaxf(fmaf(acc[5], di, bb1.y), 0.f);
    float o6 = fmaxf(fmaf(acc[6], di, bb1.z), 0.f);
    float o7 = fmaxf(fmaf(acc[7], di, bb1.w), 0.f);
    uint4 st;
    __half2* sp = (__half2*)&st;
    sp[0] = __floats2half2_rn(o0, o1);
    sp[1] = __floats2half2_rn(o2, o3);
    sp[2] = __floats2half2_rn(o4, o5);
    sp[3] = __floats2half2_rn(o6, o7);
    *(uint4*)(g_agg1h + (size_t)n * HID + j * 8) = st;
}

// ---------------- GEMM2: h2h = (agg1h @ W2) * dinv  (fp16 in/out) ----------------
#define XS2_PITCH 68
__global__ void __launch_bounds__(256, 2) k_gemm2(const float* __restrict__ W2) {
    __shared__ float xs[128 * XS2_PITCH];  // 34.8 KB
    __shared__ float ws[HID * 64];         // 16 KB (cols padded 40->64)
    const int tid  = threadIdx.x;
    const int row0 = blockIdx.x * 128;

    #pragma unroll
    for (int i = 0; i < 16; i++) {
        int idx = tid + i * 256;
        int k = idx >> 6, c = idx & 63;
        ws[idx] = (c < NCLS) ? W2[k * NCLS + c] : 0.0f;
    }
    #pragma unroll
    for (int i = 0; i < 4; i++) {
        int f = tid + i * 256;            // [0, 1024)
        int r = f >> 3;
        int c = f & 7;
        float v[8] = {0.f, 0.f, 0.f, 0.f, 0.f, 0.f, 0.f, 0.f};
        if (row0 + r < NNODES) {
            uint4 h = *(const uint4*)(g_agg1h + (size_t)(row0 + r) * HID + c * 8);
            float2 f0 = h2tof2(h.x), f1 = h2tof2(h.y), f2 = h2tof2(h.z), f3 = h2tof2(h.w);
            v[0] = f0.x; v[1] = f0.y; v[2] = f1.x; v[3] = f1.y;
            v[4] = f2.x; v[5] = f2.y; v[6] = f3.x; v[7] = f3.y;
        }
        float* xp = xs + r * XS2_PITCH + c * 8;
        *(float4*)(xp)     = make_float4(v[0], v[1], v[2], v[3]);
        *(float4*)(xp + 4) = make_float4(v[4], v[5], v[6], v[7]);
    }
    __syncthreads();

    const int rp = tid >> 4;
    const int cg = tid & 15;
    if (cg >= 10) return;
    const float* wcol = ws + cg * 4;
    const float* xr = xs + (rp * 8) * XS2_PITCH;

    u64 acc[8][2];
    #pragma unroll
    for (int r = 0; r < 8; r++) { acc[r][0] = 0ull; acc[r][1] = 0ull; }

    #pragma unroll 2
    for (int k = 0; k < HID; k += 4) {
        float4 xa[8];
        #pragma unroll
        for (int r = 0; r < 8; r++)
            xa[r] = *(const float4*)(xr + r * XS2_PITCH + k);
        #pragma unroll
        for (int kk = 0; kk < 4; kk++) {
            W4 w;
            w.v = *(const float4*)(wcol + (k + kk) * 64);
            #pragma unroll
            for (int r = 0; r < 8; r++) {
                u64 xv = pack2((&xa[r].x)[kk]);
                acc[r][0] = ffma2(w.u.lo, xv, acc[r][0]);
                acc[r][1] = ffma2(w.u.hi, xv, acc[r][1]);
            }
        }
    }

    #pragma unroll
    for (int r = 0; r < 8; r++) {
        int row = row0 + rp * 8 + r;
        if (row >= NNODES) continue;
        float di = g_dinv[row];
        F2 a0, a1;
        a0.u = acc[r][0]; a1.u = acc[r][1];
        uint2 st;
        __half2* sp = (__half2*)&st;
        sp[0] = __floats2half2_rn(a0.f.x * di, a0.f.y * di);
        sp[1] = __floats2half2_rn(a1.f.x * di, a1.f.y * di);
        *(uint2*)(g_h2h + (size_t)row * NCLS + cg * 4) = st;
    }
}

// ---------------- agg2: out[n] = (h2h[n] + sum h2h[src]) * dinv[n] + b2 ----------------
// 5 lanes per node; lane j owns 8 halves (16B).
__global__ void __launch_bounds__(256) k_agg2(const float* __restrict__ b2,
                                              float* __restrict__ out) {
    int t = blockIdx.x * 256 + threadIdx.x;
    int n = t / 5;
    if (n >= NNODES) return;
    int j = t - n * 5;

    int p0, p1;
    node_range(n, p0, p1);

    float acc[8];
    {
        uint4 v = *(const uint4*)(g_h2h + (size_t)n * NCLS + j * 8);
        float2 f0 = h2tof2(v.x), f1 = h2tof2(v.y), f2 = h2tof2(v.z), f3 = h2tof2(v.w);
        acc[0] = f0.x; acc[1] = f0.y; acc[2] = f1.x; acc[3] = f1.y;
        acc[4] = f2.x; acc[5] = f2.y; acc[6] = f3.x; acc[7] = f3.y;
    }
    int p = p0;
    for (; p + 8 <= p1; p += 8) {
        int s[8];
        #pragma unroll
        for (int q = 0; q < 8; q++) s[q] = g_csr_src[p + q];
        uint4 v[8];
        #pragma unroll
        for (int q = 0; q < 8; q++)
            v[q] = *(const uint4*)(g_h2h + (size_t)s[q] * NCLS + j * 8);
        #pragma unroll
        for (int q = 0; q < 8; q++) {
            float2 f0 = h2tof2(v[q].x), f1 = h2tof2(v[q].y);
            float2 f2 = h2tof2(v[q].z), f3 = h2tof2(v[q].w);
            acc[0] += f0.x; acc[1] += f0.y; acc[2] += f1.x; acc[3] += f1.y;
            acc[4] += f2.x; acc[5] += f2.y; acc[6] += f3.x; acc[7] += f3.y;
        }
    }
    for (; p < p1; p++) {
        int s = g_csr_src[p];
        uint4 v = *(const uint4*)(g_h2h + (size_t)s * NCLS + j * 8);
        float2 f0 = h2tof2(v.x), f1 = h2tof2(v.y), f2 = h2tof2(v.z), f3 = h2tof2(v.w);
        acc[0] += f0.x; acc[1] += f0.y; acc[2] += f1.x; acc[3] += f1.y;
        acc[4] += f2.x; acc[5] += f2.y; acc[6] += f3.x; acc[7] += f3.y;
    }
    float di = g_dinv[n];
    float4 bb0 = *(const float4*)(b2 + j * 8);
    float4 bb1 = *(const float4*)(b2 + j * 8 + 4);
    float* op = out + (size_t)n * NCLS + j * 8;
    *(float4*)(op)     = make_float4(fmaf(acc[0], di, bb0.x), fmaf(acc[1], di, bb0.y),
                                     fmaf(acc[2], di, bb0.z), fmaf(acc[3], di, bb0.w));
    *(float4*)(op + 4) = make_float4(fmaf(acc[4], di, bb1.x), fmaf(acc[5], di, bb1.y),
                                     fmaf(acc[6], di, bb1.z), fmaf(acc[7], di, bb1.w));
}

// ---------------- launch ----------------
extern "C" void kernel_launch(void* const* d_in, const int* in_sizes, int n_in,
                              void* d_out, int out_size) {
    const float* x   = (const float*)d_in[0];
    const int*   ei  = (const int*)d_in[1];
    const float* W1  = (const float*)d_in[2];
    const float* b1  = (const float*)d_in[3];
    const float* W2  = (const float*)d_in[4];
    const float* b2  = (const float*)d_in[5];
    float* out = (float*)d_out;

    const int* src = ei;
    const int* dst = ei + NEDGES;

    // CSR build + dinv (rank-based fill: no atomics in fill)
    k_zero<<<(NNODES + 255) / 256, 256>>>();
    k_hist<<<(NEDGES + 255) / 256, 256>>>(dst);
    k_scan1<<<SCAN_BLOCKS, 1024>>>();
    k_fill<<<(NEDGES + 255) / 256, 256>>>(src, dst);

    // layer 1
    k_gemm1<<<(NNODES + 127) / 128, 256>>>(x, W1);
    k_agg1<<<(NNODES * 8 + 255) / 256, 256>>>(b1);

    // layer 2
    k_gemm2<<<(NNODES + 127) / 128, 256>>>(W2);
    k_agg2<<<(NNODES * 5 + 255) / 256, 256>>>(b2, out);
}

// round 17
// speedup vs baseline: 1.2581x; 1.1034x over previous
#include <cuda_runtime.h>
#include <cuda_fp16.h>
#include <mma.h>
#include <cstdint>

using namespace nvcuda;

#define NNODES 100000
#define NEDGES 1600000
#define FIN    128
#define HID    64
#define NCLS   40

#define SCAN_BLOCKS 98   // 98 * 1024 >= NNODES

// ---------------- device scratch (allocation-free) ----------------
__device__ int    g_hist[NNODES];
__device__ int    g_rank[NEDGES];
__device__ int    g_offs[NNODES];
__device__ int    g_boff[SCAN_BLOCKS];
__device__ int    g_total;
__device__ int    g_csr_src[NEDGES];
__device__ float  g_dinv[NNODES];
__device__ __half g_h1h[(size_t)NNODES * HID];
__device__ __half g_agg1h[(size_t)NNODES * HID];
__device__ __half g_h2h[(size_t)NNODES * NCLS];

// ---------------- helpers ----------------
__device__ __forceinline__ float2 h2tof2(uint32_t h) {
    __half2 hh = *reinterpret_cast<__half2*>(&h);
    return __half22float2(hh);
}

__device__ __forceinline__ void node_range(int n, int& p0, int& p1) {
    p0 = g_offs[n] + g_boff[n >> 10];
    int m = n + 1;
    if ((m >> 10) == (n >> 10) && m < NNODES)
        p1 = g_offs[m] + g_boff[m >> 10];
    else
        p1 = p0 + g_hist[n];
}

// ---------------- CSR build ----------------
__global__ void k_zero() {
    int i = blockIdx.x * blockDim.x + threadIdx.x;
    if (i < NNODES) g_hist[i] = 0;
    if (i == 0) g_total = 0;
}
// 4-edge-batched histogram with rank recording
__global__ void k_hist(const int* __restrict__ dst) {
    int e0 = (blockIdx.x * blockDim.x + threadIdx.x) * 4;
    if (e0 >= NEDGES) return;
    int4 d = *(const int4*)(dst + e0);
    int4 r;
    r.x = atomicAdd(&g_hist[d.x], 1);
    r.y = atomicAdd(&g_hist[d.y], 1);
    r.z = atomicAdd(&g_hist[d.z], 1);
    r.w = atomicAdd(&g_hist[d.w], 1);
    *(int4*)(g_rank + e0) = r;
}
// block scan + atomic chunk reservation
__global__ void __launch_bounds__(1024) k_scan1() {
    __shared__ int sh[1024];
    int i = blockIdx.x * 1024 + threadIdx.x;
    int h = (i < NNODES) ? g_hist[i] : 0;
    sh[threadIdx.x] = h;
    __syncthreads();
    #pragma unroll
    for (int ofs = 1; ofs < 1024; ofs <<= 1) {
        int v = (threadIdx.x >= ofs) ? sh[threadIdx.x - ofs] : 0;
        __syncthreads();
        sh[threadIdx.x] += v;
        __syncthreads();
    }
    if (i < NNODES) {
        g_offs[i] = sh[threadIdx.x] - h;
        g_dinv[i] = rsqrtf((float)(h + 1));
    }
    if (threadIdx.x == 1023)
        g_boff[blockIdx.x] = atomicAdd(&g_total, sh[1023]);
}
// 4-edge-batched atomic-free scatter
__global__ void k_fill(const int* __restrict__ src, const int* __restrict__ dst) {
    int e0 = (blockIdx.x * blockDim.x + threadIdx.x) * 4;
    if (e0 >= NEDGES) return;
    int4 d = *(const int4*)(dst + e0);
    int4 r = *(const int4*)(g_rank + e0);
    int4 s = *(const int4*)(src + e0);
    g_csr_src[g_offs[d.x] + g_boff[d.x >> 10] + r.x] = s.x;
    g_csr_src[g_offs[d.y] + g_boff[d.y >> 10] + r.y] = s.y;
    g_csr_src[g_offs[d.z] + g_boff[d.z >> 10] + r.z] = s.z;
    g_csr_src[g_offs[d.w] + g_boff[d.w >> 10] + r.w] = s.w;
}

// ---------------- GEMM1 (wmma): h1h = (x @ W1) * dinv ----------------
#define XH_LDM 136
#define WH_LDM 72
__global__ void __launch_bounds__(256, 2) k_gemm1(const float* __restrict__ x,
                                                  const float* __restrict__ W1) {
    __shared__ __half xh[128 * XH_LDM];   // 34.8 KB
    __shared__ __half wh[FIN * WH_LDM];   // 18.4 KB
    __shared__ float  sbuf[128 * HID];    // 32 KB
    const int tid  = threadIdx.x;
    const int row0 = blockIdx.x * 128;

    #pragma unroll
    for (int i = 0; i < 32; i++) {
        int idx = tid + i * 256;
        int k = idx >> 6, c = idx & 63;
        wh[k * WH_LDM + c] = __float2half_rn(W1[idx]);
    }
    #pragma unroll
    for (int i = 0; i < 16; i++) {
        int f = tid + i * 256;
        int r = f >> 5;
        int o = (f & 31) << 2;
        float4 v = make_float4(0.f, 0.f, 0.f, 0.f);
        if (row0 + r < NNODES) v = *(const float4*)(x + (size_t)(row0 + r) * FIN + o);
        __half2* hp = (__half2*)(xh + r * XH_LDM + o);
        hp[0] = __floats2half2_rn(v.x, v.y);
        hp[1] = __floats2half2_rn(v.z, v.w);
    }
    __syncthreads();

    const int w = tid >> 5;

    wmma::fragment<wmma::accumulator, 16, 16, 16, float> c[4];
    #pragma unroll
    for (int j = 0; j < 4; j++) wmma::fill_fragment(c[j], 0.0f);

    #pragma unroll
    for (int k8 = 0; k8 < FIN / 16; k8++) {
        wmma::fragment<wmma::matrix_a, 16, 16, 16, __half, wmma::row_major> a;
        wmma::load_matrix_sync(a, xh + (w * 16) * XH_LDM + k8 * 16, XH_LDM);
        #pragma unroll
        for (int j = 0; j < 4; j++) {
            wmma::fragment<wmma::matrix_b, 16, 16, 16, __half, wmma::row_major> b;
            wmma::load_matrix_sync(b, wh + (k8 * 16) * WH_LDM + j * 16, WH_LDM);
            wmma::mma_sync(c[j], a, b, c[j]);
        }
    }

    #pragma unroll
    for (int j = 0; j < 4; j++)
        wmma::store_matrix_sync(sbuf + (w * 16) * HID + j * 16, c[j], HID, wmma::mem_row_major);
    __syncwarp();

    const int lane = tid & 31;
    const int lr   = lane >> 1;
    const int hs   = lane & 1;
    const int row  = w * 16 + lr;
    const int grow = row0 + row;
    if (grow < NNODES) {
        float di = g_dinv[grow];
        const float* sp = sbuf + row * HID + hs * 32;
        __half* hp = g_h1h + (size_t)grow * HID + hs * 32;
        #pragma unroll
        for (int q = 0; q < 4; q++) {
            float4 v0 = *(const float4*)(sp + q * 8);
            float4 v1 = *(const float4*)(sp + q * 8 + 4);
            uint4 st;
            __half2* s2 = (__half2*)&st;
            s2[0] = __floats2half2_rn(v0.x * di, v0.y * di);
            s2[1] = __floats2half2_rn(v0.z * di, v0.w * di);
            s2[2] = __floats2half2_rn(v1.x * di, v1.y * di);
            s2[3] = __floats2half2_rn(v1.z * di, v1.w * di);
            *(uint4*)(hp + q * 8) = st;
        }
    }
}

// ---------------- agg1: agg1h[n] = relu((h1h[n] + sum h1h[src]) * dinv[n] + b1) ----------------
__global__ void __launch_bounds__(256) k_agg1(const float* __restrict__ b1) {
    int t = blockIdx.x * 256 + threadIdx.x;
    int n = t >> 3;
    if (n >= NNODES) return;
    int j = t & 7;

    int p0, p1;
    node_range(n, p0, p1);

    float acc[8];
    {
        uint4 v = *(const uint4*)(g_h1h + (size_t)n * HID + j * 8);
        float2 f0 = h2tof2(v.x), f1 = h2tof2(v.y), f2 = h2tof2(v.z), f3 = h2tof2(v.w);
        acc[0] = f0.x; acc[1] = f0.y; acc[2] = f1.x; acc[3] = f1.y;
        acc[4] = f2.x; acc[5] = f2.y; acc[6] = f3.x; acc[7] = f3.y;
    }
    int p = p0;
    for (; p + 8 <= p1; p += 8) {
        int s[8];
        #pragma unroll
        for (int q = 0; q < 8; q++) s[q] = g_csr_src[p + q];
        uint4 v[8];
        #pragma unroll
        for (int q = 0; q < 8; q++)
            v[q] = *(const uint4*)(g_h1h + (size_t)s[q] * HID + j * 8);
        #pragma unroll
        for (int q = 0; q < 8; q++) {
            float2 f0 = h2tof2(v[q].x), f1 = h2tof2(v[q].y);
            float2 f2 = h2tof2(v[q].z), f3 = h2tof2(v[q].w);
            acc[0] += f0.x; acc[1] += f0.y; acc[2] += f1.x; acc[3] += f1.y;
            acc[4] += f2.x; acc[5] += f2.y; acc[6] += f3.x; acc[7] += f3.y;
        }
    }
    for (; p < p1; p++) {
        int s = g_csr_src[p];
        uint4 v = *(const uint4*)(g_h1h + (size_t)s * HID + j * 8);
        float2 f0 = h2tof2(v.x), f1 = h2tof2(v.y), f2 = h2tof2(v.z), f3 = h2tof2(v.w);
        acc[0] += f0.x; acc[1] += f0.y; acc[2] += f1.x; acc[3] += f1.y;
        acc[4] += f2.x; acc[5] += f2.y; acc[6] += f3.x; acc[7] += f3.y;
    }
    float di = g_dinv[n];
    float4 bb0 = *(const float4*)(b1 + j * 8);
    float4 bb1 = *(const float4*)(b1 + j * 8 + 4);
    float o0 = fmaxf(fmaf(acc[0], di, bb0.x), 0.f);
    float o1 = fmaxf(fmaf(acc[1], di, bb0.y), 0.f);
    float o2 = fmaxf(fmaf(acc[2], di, bb0.z), 0.f);
    float o3 = fmaxf(fmaf(acc[3], di, bb0.w), 0.f);
    float o4 = fmaxf(fmaf(acc[4], di, bb1.x), 0.f);
    float o5 = fmaxf(fmaf(acc[5], di, bb1.y), 0.f);
    float o6 = fmaxf(fmaf(acc[6], di, bb1.z), 0.f);
    float o7 = fmaxf(fmaf(acc[7], di, bb1.w), 0.f);
    uint4 st;
    __half2* sp = (__half2*)&st;
    sp[0] = __floats2half2_rn(o0, o1);
    sp[1] = __floats2half2_rn(o2, o3);
    sp[2] = __floats2half2_rn(o4, o5);
    sp[3] = __floats2half2_rn(o6, o7);
    *(uint4*)(g_agg1h + (size_t)n * HID + j * 8) = st;
}

// ---------------- GEMM2 (wmma): h2h = (agg1h @ W2) * dinv ----------------
// 8 warps, 128-row tile; warp w: rows w*16..+15 x 48 padded cols (40 real).
#define AH_LDM 72    // halves
#define W2_LDM 48    // halves (cols padded 40->48)
#define SB_LDM 48    // floats
__global__ void __launch_bounds__(256, 2) k_gemm2(const float* __restrict__ W2) {
    __shared__ __half ah[128 * AH_LDM];   // 18.4 KB
    __shared__ __half w2h[HID * W2_LDM];  // 6.1 KB
    __shared__ float  sbuf[128 * SB_LDM]; // 24.6 KB
    const int tid  = threadIdx.x;
    const int row0 = blockIdx.x * 128;

    // W2 [64][40] fp32 -> w2h [64][48] fp16 zero-padded
    #pragma unroll
    for (int i = 0; i < 12; i++) {
        int idx = tid + i * 256;          // [0, 3072)
        int k = idx / 48, c = idx - k * 48;
        w2h[idx] = __float2half_rn((c < NCLS) ? W2[k * NCLS + c] : 0.0f);
    }
    // agg1h tile: raw fp16 copy, 128 rows x 64 halves = 1024 uint4 chunks
    #pragma unroll
    for (int i = 0; i < 4; i++) {
        int f = tid + i * 256;
        int r = f >> 3;
        int c = f & 7;
        uint4 v = make_uint4(0, 0, 0, 0);
        if (row0 + r < NNODES)
            v = *(const uint4*)(g_agg1h + (size_t)(row0 + r) * HID + c * 8);
        *(uint4*)(ah + r * AH_LDM + c * 8) = v;
    }
    __syncthreads();

    const int w = tid >> 5;

    wmma::fragment<wmma::accumulator, 16, 16, 16, float> c[3];
    #pragma unroll
    for (int j = 0; j < 3; j++) wmma::fill_fragment(c[j], 0.0f);

    #pragma unroll
    for (int k8 = 0; k8 < HID / 16; k8++) {
        wmma::fragment<wmma::matrix_a, 16, 16, 16, __half, wmma::row_major> a;
        wmma::load_matrix_sync(a, ah + (w * 16) * AH_LDM + k8 * 16, AH_LDM);
        #pragma unroll
        for (int j = 0; j < 3; j++) {
            wmma::fragment<wmma::matrix_b, 16, 16, 16, __half, wmma::row_major> b;
            wmma::load_matrix_sync(b, w2h + (k8 * 16) * W2_LDM + j * 16, W2_LDM);
            wmma::mma_sync(c[j], a, b, c[j]);
        }
    }

    #pragma unroll
    for (int j = 0; j < 3; j++)
        wmma::store_matrix_sync(sbuf + (w * 16) * SB_LDM + j * 16, c[j], SB_LDM, wmma::mem_row_major);
    __syncwarp();

    // epilogue: 16 rows x 40 cols = 320 half2 units, 32 lanes x 10 iters
    const int lane = tid & 31;
    #pragma unroll
    for (int it = 0; it < 10; it++) {
        int e = lane + it * 32;           // [0, 320)
        int r = e / 20;
        int c2 = e - r * 20;              // half2 col index (0..19)
        int grow = row0 + w * 16 + r;
        if (grow < NNODES) {
            float di = g_dinv[grow];
            const float* sp = sbuf + (w * 16 + r) * SB_LDM + c2 * 2;
            __half2 hv = __floats2half2_rn(sp[0] * di, sp[1] * di);
            *(__half2*)(g_h2h + (size_t)grow * NCLS + c2 * 2) = hv;
        }
    }
}

// ---------------- agg2: out[n] = (h2h[n] + sum h2h[src]) * dinv[n] + b2 ----------------
__global__ void __launch_bounds__(256) k_agg2(const float* __restrict__ b2,
                                              float* __restrict__ out) {
    int t = blockIdx.x * 256 + threadIdx.x;
    int n = t / 5;
    if (n >= NNODES) return;
    int j = t - n * 5;

    int p0, p1;
    node_range(n, p0, p1);

    float acc[8];
    {
        uint4 v = *(const uint4*)(g_h2h + (size_t)n * NCLS + j * 8);
        float2 f0 = h2tof2(v.x), f1 = h2tof2(v.y), f2 = h2tof2(v.z), f3 = h2tof2(v.w);
        acc[0] = f0.x; acc[1] = f0.y; acc[2] = f1.x; acc[3] = f1.y;
        acc[4] = f2.x; acc[5] = f2.y; acc[6] = f3.x; acc[7] = f3.y;
    }
    int p = p0;
    for (; p + 8 <= p1; p += 8) {
        int s[8];
        #pragma unroll
        for (int q = 0; q < 8; q++) s[q] = g_csr_src[p + q];
        uint4 v[8];
        #pragma unroll
        for (int q = 0; q < 8; q++)
            v[q] = *(const uint4*)(g_h2h + (size_t)s[q] * NCLS + j * 8);
        #pragma unroll
        for (int q = 0; q < 8; q++) {
            float2 f0 = h2tof2(v[q].x), f1 = h2tof2(v[q].y);
            float2 f2 = h2tof2(v[q].z), f3 = h2tof2(v[q].w);
            acc[0] += f0.x; acc[1] += f0.y; acc[2] += f1.x; acc[3] += f1.y;
            acc[4] += f2.x; acc[5] += f2.y; acc[6] += f3.x; acc[7] += f3.y;
        }
    }
    for (; p < p1; p++) {
        int s = g_csr_src[p];
        uint4 v = *(const uint4*)(g_h2h + (size_t)s * NCLS + j * 8);
        float2 f0 = h2tof2(v.x), f1 = h2tof2(v.y), f2 = h2tof2(v.z), f3 = h2tof2(v.w);
        acc[0] += f0.x; acc[1] += f0.y; acc[2] += f1.x; acc[3] += f1.y;
        acc[4] += f2.x; acc[5] += f2.y; acc[6] += f3.x; acc[7] += f3.y;
    }
    float di = g_dinv[n];
    float4 bb0 = *(const float4*)(b2 + j * 8);
    float4 bb1 = *(const float4*)(b2 + j * 8 + 4);
    float* op = out + (size_t)n * NCLS + j * 8;
    *(float4*)(op)     = make_float4(fmaf(acc[0], di, bb0.x), fmaf(acc[1], di, bb0.y),
                                     fmaf(acc[2], di, bb0.z), fmaf(acc[3], di, bb0.w));
    *(float4*)(op + 4) = make_float4(fmaf(acc[4], di, bb1.x), fmaf(acc[5], di, bb1.y),
                                     fmaf(acc[6], di, bb1.z), fmaf(acc[7], di, bb1.w));
}

// ---------------- launch ----------------
extern "C" void kernel_launch(void* const* d_in, const int* in_sizes, int n_in,
                              void* d_out, int out_size) {
    const float* x   = (const float*)d_in[0];
    const int*   ei  = (const int*)d_in[1];
    const float* W1  = (const float*)d_in[2];
    const float* b1  = (const float*)d_in[3];
    const float* W2  = (const float*)d_in[4];
    const float* b2  = (const float*)d_in[5];
    float* out = (float*)d_out;

    const int* src = ei;
    const int* dst = ei + NEDGES;

    // CSR build + dinv
    k_zero<<<(NNODES + 255) / 256, 256>>>();
    k_hist<<<(NEDGES / 4 + 255) / 256, 256>>>(dst);
    k_scan1<<<SCAN_BLOCKS, 1024>>>();
    k_fill<<<(NEDGES / 4 + 255) / 256, 256>>>(src, dst);

    // layer 1
    k_gemm1<<<(NNODES + 127) / 128, 256>>>(x, W1);
    k_agg1<<<(NNODES * 8 + 255) / 256, 256>>>(b1);

    // layer 2
    k_gemm2<<<(NNODES + 127) / 128, 256>>>(W2);
    k_agg2<<<(NNODES * 5 + 255) / 256, 256>>>(b2, out);
}